// round 11
// baseline (speedup 1.0000x reference)
#include <cuda_runtime.h>
#include <cuda_bf16.h>
#include <cstdint>

// ---------------- problem constants ----------------
#define BATCH   16
#define TT      8192
#define NPRE    128
#define NPOST   128
#define CHUNK   1024              // timesteps per CTA
#define SC      64                // sub-chunk (MMA K tile / pipeline block)
#define NBLK    (CHUNK / SC)      // 16
#define NCTA    (BATCH * TT / CHUNK)  // 128
#define LWIN    60                // filter length (taps 1..59)

#define TAU_F       20.0f
#define A_PLUS_F    0.005f
#define A_MINUS_F   0.00525f
#define TARGET_RATE 0.1f
#define HOM_RATE    0.001f
#define TAU_HOM     1000.0f

// ---------------- smem layout (164 KB, 1 CTA/SM) ----------------
#define POST_SLOT_BYTES (SC * 128 * 4)        // 32768; 4-slot ring
#define STRIDE_H        72                    // halves per row (conflict-free ldmatrix)
#define MAT_BYTES       (128 * STRIDE_H * 2)  // 18432 (one of preT / hT)

#define OFF_POST 0
#define OFF_PRET (4 * POST_SLOT_BYTES)        // 131072
#define OFF_HT   (OFF_PRET + MAT_BYTES)       // 149504
#define SMEM_BYTES (OFF_HT + MAT_BYTES)       // 167936

// ---------------- scratch (static device, no allocs) ----------------
__device__ float g_partials[(size_t)NCTA * NPRE * NPOST];   // 8 MB
__device__ float g_part2[8 * NPRE * NPOST];                 // 512 KB
__device__ float g_colsum_part[NCTA * NPOST];               // 64 KB
__device__ float g_errq[NPOST];

__device__ __forceinline__ float decode_dt(const void* p) {
    if (p == nullptr) return 1.0f;
    int iv = *(const int*)p;
    if (iv >= 1 && iv <= 1000000) return (float)iv;   // int32/int64 low word
    return *(const float*)p;                          // float32 bits
}
__device__ __forceinline__ unsigned smem_u32(const void* p) {
    return (unsigned)__cvta_generic_to_shared(p);
}

// ==========================================================================
// Kernel 1: pipelined filter + transpose + bf16 HMMA partial GEMM
// grid = 128 CTAs (one (b, 1024-t) unit each), 256 threads
//   per iter: [h-filter (tid<128) || pre stmatrix (tid>=128)] -> MMA (all 8 warps)
//   post: 4-slot cp.async ring, depth-2 prefetch
// ==========================================================================
__global__ __launch_bounds__(256)
void stdp_main(const float* __restrict__ pre, const float* __restrict__ post,
               const void* __restrict__ dtp)
{
    extern __shared__ char smem[];
    char*          post_base = smem + OFF_POST;                 // 4 slots [64 t][128 q] fp32
    __nv_bfloat16* preT      = (__nv_bfloat16*)(smem + OFF_PRET); // [128 p][72 t] bf16
    __nv_bfloat16* hT        = (__nv_bfloat16*)(smem + OFF_HT);   // [128 q][72 t] bf16

    const int tid  = threadIdx.x;
    const int lane = tid & 31;
    const int w    = tid >> 5;
    const int u    = blockIdx.x;
    const int b    = u >> 3;               // 8 units per batch
    const int t0   = (u & 7) * CHUNK;

    const float dt  = decode_dt(dtp);
    const float r   = expf(-dt / TAU_F);
    const float g0  = A_PLUS_F - A_MINUS_F;          // TAU_PLUS == TAU_MINUS
    const float c1  = r * g0;
    const float c60 = g0 * expf(-60.0f * dt / TAU_F);

    const char*  postg = (const char*)(post + (size_t)b * TT * 128);
    const float* preg  = pre + (size_t)b * TT * 128;

    // stage post block k -> ring slot k%4 (zero-fill past T)
    auto load_post = [&](int k) {
        const int tb0 = t0 + k * SC;
        #pragma unroll
        for (int i = tid; i < SC * 32; i += 256) {            // 2048 x 16B
            const int rr = i >> 5, c4 = i & 31;
            const int t  = tb0 + rr;
            const unsigned dst = smem_u32(post_base + (k & 3) * POST_SLOT_BYTES
                                          + rr * 512 + c4 * 16);
            const char* src = postg + ((size_t)(t < TT ? t : 0) * 512 + c4 * 16);
            const int ss = (t < TT) ? 16 : 0;
            asm volatile("cp.async.cg.shared.global [%0], [%1], 16, %2;\n"
                         :: "r"(dst), "l"(src), "r"(ss));
        }
        asm volatile("cp.async.commit_group;\n");
    };

    // MMA accumulators: warp w -> p in [ (w&3)*32, +32 ), q in [ (w>>2)*64, +64 )
    float acc[2][8][4];
    #pragma unroll
    for (int mt = 0; mt < 2; ++mt)
        #pragma unroll
        for (int nt = 0; nt < 8; ++nt)
            #pragma unroll
            for (int c = 0; c < 4; ++c) acc[mt][nt][c] = 0.0f;

    float hcarry = 0.0f;   // filter state (tid<128, one q each)
    float colsum = 0.0f;

    // prologue: boundary block NBLK + first two compute blocks (depth-2)
    load_post(NBLK);
    load_post(NBLK - 1);
    load_post(NBLK - 2);

    for (int kt = NBLK - 1; kt >= 0; --kt) {
        // ---- transpose warps: issue pre LDGs early (overlap the wait) ----
        unsigned regs[8][4];
        if (w >= 4) {
            const int wi = w - 4;
            const float* pg = preg + (size_t)(t0 + kt * SC) * 128;
            #pragma unroll
            for (int it = 0; it < 8; ++it) {
                const int tile = wi * 8 + it;
                const int tb = tile & 7;      // t block of 8
                const int pb = tile >> 3;     // p block of 32
                const int trow = tb * 8 + (lane >> 2);
                const int pc   = pb * 32 + 2 * (lane & 3);
                #pragma unroll
                for (int j = 0; j < 4; ++j) {
                    const float2 v = *(const float2*)(pg + (size_t)trow * 128 + pc + 8 * j);
                    // pre in {0.0f,1.0f}: bf16 bits == high 16 bits of f32 (EXACT)
                    regs[it][j] = __byte_perm(__float_as_uint(v.x),
                                              __float_as_uint(v.y), 0x7632);
                }
            }
        }

        // blocks kt and kt+1 must be resident; kt-1 may stay in flight
        if (kt >= 1) asm volatile("cp.async.wait_group 1;\n");
        else         asm volatile("cp.async.wait_group 0;\n");
        __syncthreads();    // staged post visible; previous MMA done with preT/hT

        if (kt >= 2) load_post(kt - 2);   // slot (kt+2)&3 free (read finished last iter)

        const float* cur = (const float*)(post_base + (kt & 3) * POST_SLOT_BYTES);
        const float* nxt = (const float*)(post_base + ((kt + 1) & 3) * POST_SLOT_BYTES);

        if (tid < 128) {
            // ---------- h filter (exact backward recurrence) -> hT[q][t] bf16 ----------
            const int q = tid;
            if (kt == NBLK - 1) {
                // init h[last t of chunk] by direct truncated 59-tap sum
                float hh = 0.0f, wc = g0;
                #pragma unroll 4
                for (int tau = 1; tau < LWIN; ++tau) {
                    wc *= r;
                    hh += wc * nxt[(tau - 1) * 128 + q];
                }
                hcarry = hh;
            }
            #pragma unroll
            for (int g8 = SC / 8 - 1; g8 >= 0; --g8) {
                unsigned hp0 = 0, hp1 = 0, hp2 = 0, hp3 = 0, stash = 0;
                #pragma unroll
                for (int e = 7; e >= 0; --e) {
                    const int lt = g8 * 8 + e;
                    const unsigned uh =
                        (unsigned)__bfloat16_as_ushort(__float2bfloat16_rn(hcarry));
                    if (e & 1) stash = uh << 16;
                    else {
                        const unsigned wv = stash | uh;
                        if (e == 0) hp0 = wv; else if (e == 2) hp1 = wv;
                        else if (e == 4) hp2 = wv; else hp3 = wv;
                    }
                    const float s1  = cur[lt * 128 + q];
                    const float s60 = (lt < 5) ? cur[(lt + 59) * 128 + q]
                                               : nxt[(lt - 5) * 128 + q];
                    colsum += s1;        // exact integer column count
                    hcarry = fmaf(r, hcarry, fmaf(c1, s1, -c60 * s60));
                }
                uint4 v; v.x = hp0; v.y = hp1; v.z = hp2; v.w = hp3;
                *(uint4*)(hT + q * STRIDE_H + g8 * 8) = v;   // conflict-free STS.128
            }
        } else {
            // ---------- stmatrix regs -> preT[p][t] ----------
            const int wi = w - 4;
            #pragma unroll
            for (int it = 0; it < 8; ++it) {
                const int tile = wi * 8 + it;
                const int tb = tile & 7;
                const int pb = tile >> 3;
                const unsigned daddr = smem_u32(
                    preT + (pb * 32 + (lane >> 3) * 8 + (lane & 7)) * STRIDE_H + tb * 8);
                asm volatile(
                    "stmatrix.sync.aligned.m8n8.x4.trans.shared.b16 [%0], {%1,%2,%3,%4};\n"
                    :: "r"(daddr), "r"(regs[it][0]), "r"(regs[it][1]),
                       "r"(regs[it][2]), "r"(regs[it][3]));
            }
        }
        __syncthreads();    // preT/hT filled

        // ---------- MMA (bf16): acc += preT^T . hT over K = SC (all 8 warps) ----------
        {
            const int pbase = (w & 3) * 32;
            const int qbase = (w >> 2) * 64;
            #pragma unroll
            for (int ks = 0; ks < SC / 16; ++ks) {
                const int k0 = ks * 16;
                unsigned a[2][4];
                #pragma unroll
                for (int mt = 0; mt < 2; ++mt) {
                    const int arow = pbase + mt * 16 + (lane & 15);
                    const int acol = k0 + ((lane >> 4) << 3);
                    const unsigned aaddr = smem_u32(preT + arow * STRIDE_H + acol);
                    asm volatile(
                        "ldmatrix.sync.aligned.m8n8.x4.shared.b16 {%0,%1,%2,%3}, [%4];\n"
                        : "=r"(a[mt][0]), "=r"(a[mt][1]), "=r"(a[mt][2]), "=r"(a[mt][3])
                        : "r"(aaddr));
                }
                #pragma unroll
                for (int nt = 0; nt < 8; ++nt) {
                    const int brow = qbase + nt * 8 + (lane & 7);
                    const int bcol = k0 + (((lane >> 3) & 1) << 3);
                    const unsigned baddr = smem_u32(hT + brow * STRIDE_H + bcol);
                    unsigned b0, b1;
                    asm volatile(
                        "ldmatrix.sync.aligned.m8n8.x2.shared.b16 {%0,%1}, [%2];\n"
                        : "=r"(b0), "=r"(b1) : "r"(baddr));
                    #pragma unroll
                    for (int mt = 0; mt < 2; ++mt) {
                        asm volatile(
                            "mma.sync.aligned.m16n8k16.row.col.f32.bf16.bf16.f32 "
                            "{%0,%1,%2,%3}, {%4,%5,%6,%7}, {%8,%9}, {%0,%1,%2,%3};\n"
                            : "+f"(acc[mt][nt][0]), "+f"(acc[mt][nt][1]),
                              "+f"(acc[mt][nt][2]), "+f"(acc[mt][nt][3])
                            : "r"(a[mt][0]), "r"(a[mt][1]), "r"(a[mt][2]), "r"(a[mt][3]),
                              "r"(b0), "r"(b1));
                    }
                }
            }
        }
    }

    // ---- write per-CTA partials (deterministic parallel reduce later) ----
    {
        const int pbase = (w & 3) * 32;
        const int qbase = (w >> 2) * 64;
        float* outp = g_partials + (size_t)u * NPRE * NPOST;
        #pragma unroll
        for (int mt = 0; mt < 2; ++mt) {
            #pragma unroll
            for (int nt = 0; nt < 8; ++nt) {
                const int p = pbase + mt * 16 + (lane >> 2);
                const int q = qbase + nt * 8 + 2 * (lane & 3);
                *(float2*)&outp[(size_t)p * 128 + q] =
                    make_float2(acc[mt][nt][0], acc[mt][nt][1]);
                *(float2*)&outp[(size_t)(p + 8) * 128 + q] =
                    make_float2(acc[mt][nt][2], acc[mt][nt][3]);
            }
        }
    }
    if (tid < 128) g_colsum_part[u * 128 + tid] = colsum;
}

// ==========================================================================
// Kernel 2: stage-1 partial reduce (128 arrays -> 8), fully parallel
// grid = 128 (8 groups x 16 idx-chunks) x 256 threads; float4
// ==========================================================================
__global__ __launch_bounds__(256)
void reduce1()
{
    const int g  = blockIdx.x >> 4;                    // 0..7
    const int c  = blockIdx.x & 15;
    const int i4 = c * 256 + threadIdx.x;              // float4 index 0..4095
    float4 s = make_float4(0.f, 0.f, 0.f, 0.f);
    #pragma unroll
    for (int a = 0; a < 16; ++a) {
        const float4 v = *(const float4*)
            &g_partials[(size_t)(g * 16 + a) * (NPRE * NPOST) + 4 * i4];
        s.x += v.x; s.y += v.y; s.z += v.z; s.w += v.w;
    }
    *(float4*)&g_part2[g * (NPRE * NPOST) + 4 * i4] = s;
}

// ==========================================================================
// Kernel 3: homeostatic rate error per q (1024 threads, smem tree)
// ==========================================================================
__global__ void errq_kernel(const void* __restrict__ dtp)
{
    __shared__ float red[8][128];
    const int q = threadIdx.x & 127;
    const int c = threadIdx.x >> 7;                    // 0..7, 16 CTAs each
    float s = 0.0f;
    #pragma unroll
    for (int i = 0; i < NCTA / 8; ++i)
        s += g_colsum_part[(c * (NCTA / 8) + i) * NPOST + q];
    red[c][q] = s;
    __syncthreads();
    if (threadIdx.x < 128) {
        float tot = 0.0f;
        #pragma unroll
        for (int c2 = 0; c2 < 8; ++c2) tot += red[c2][q];
        const float dt    = decode_dt(dtp);
        const float alpha = dt / TAU_HOM;
        const float mean  = tot / (float)(BATCH * TT);
        g_errq[q] = ((1.0f - alpha) * TARGET_RATE + alpha * mean) - TARGET_RATE;
    }
}

// ==========================================================================
// Kernel 4: stage-2 reduce + homeostasis -> out (float4)
// ==========================================================================
__global__ __launch_bounds__(256)
void finalize2(const float* __restrict__ weights, float* __restrict__ out)
{
    const int i4 = blockIdx.x * blockDim.x + threadIdx.x;    // 0..4095 (x4 floats)
    float4 s = make_float4(0.f, 0.f, 0.f, 0.f);
    #pragma unroll
    for (int g = 0; g < 8; ++g) {
        const float4 v = *(const float4*)&g_part2[g * (NPRE * NPOST) + 4 * i4];
        s.x += v.x; s.y += v.y; s.z += v.z; s.w += v.w;
    }
    const float inv = 1.0f / (float)(BATCH * TT);            // 2^-17 exact
    const int qb = (4 * i4) & 127;
    const float4 wv = *(const float4*)&weights[4 * i4];
    float4 o;
    o.x = s.x * inv - HOM_RATE * g_errq[qb + 0] * wv.x;
    o.y = s.y * inv - HOM_RATE * g_errq[qb + 1] * wv.y;
    o.z = s.z * inv - HOM_RATE * g_errq[qb + 2] * wv.z;
    o.w = s.w * inv - HOM_RATE * g_errq[qb + 3] * wv.w;
    *(float4*)&out[4 * i4] = o;
}

// ==========================================================================
extern "C" void kernel_launch(void* const* d_in, const int* in_sizes, int n_in,
                              void* d_out, int out_size)
{
    const float* pre     = (const float*)d_in[0];
    const float* post    = (const float*)d_in[1];
    const float* weights = (const float*)d_in[2];
    const void*  dtp     = (n_in > 3) ? d_in[3] : nullptr;

    cudaFuncSetAttribute(stdp_main, cudaFuncAttributeMaxDynamicSharedMemorySize, SMEM_BYTES);
    stdp_main<<<NCTA, 256, SMEM_BYTES>>>(pre, post, dtp);
    reduce1<<<128, 256>>>();
    errq_kernel<<<1, 1024>>>(dtp);
    finalize2<<<(NPRE * NPOST) / 4 / 256, 256>>>(weights, (float*)d_out);
    (void)in_sizes; (void)out_size;
}

// round 14
// speedup vs baseline: 1.1912x; 1.1912x over previous
#include <cuda_runtime.h>
#include <cuda_bf16.h>
#include <cstdint>

// ---------------- problem constants ----------------
#define BATCH   16
#define TT      8192
#define NPRE    128
#define NPOST   128
#define CHUNK   1024              // timesteps per CTA
#define SC      64                // sub-chunk (MMA K tile / pipeline block)
#define NBLK    (CHUNK / SC)      // 16
#define NCTA    (BATCH * TT / CHUNK)  // 128
#define LWIN    60                // filter length (taps 1..59)

#define TAU_F       20.0f
#define A_PLUS_F    0.005f
#define A_MINUS_F   0.00525f
#define TARGET_RATE 0.1f
#define HOM_RATE    0.001f
#define TAU_HOM     1000.0f

// ---------------- smem layout (192 KB, 1 CTA/SM) ----------------
#define POST_SLOT_BYTES (SC * 128 * 4)        // 32768; 4-slot ring
#define TILE_BYTES      (128 * 64 * 2)        // 16384: [128 rows][64 bf16] packed, XOR-swizzled
#define SET_BYTES       (2 * TILE_BYTES)      // preT + hT
#define OFF_TILES       (4 * POST_SLOT_BYTES) // 131072
#define SMEM_BYTES      (OFF_TILES + 2 * SET_BYTES)   // 196608

// packed 128B-row swizzle: 16B segment 'bytecol' of 'row' lands at
//   row*128 + (bytecol ^ ((row&7)<<4))   -- conflict-free for 8-row groups

// ---------------- scratch (static device, no allocs) ----------------
__device__ float g_partials[(size_t)NCTA * NPRE * NPOST];   // 8 MB
__device__ float g_part2[8 * NPRE * NPOST];                 // 512 KB
__device__ float g_colsum_part[NCTA * NPOST];               // 64 KB

__device__ __forceinline__ float decode_dt(const void* p) {
    if (p == nullptr) return 1.0f;
    int iv = *(const int*)p;
    if (iv >= 1 && iv <= 1000000) return (float)iv;   // int32/int64 low word
    return *(const float*)p;                          // float32 bits
}
__device__ __forceinline__ unsigned smem_u32(const void* p) {
    return (unsigned)__cvta_generic_to_shared(p);
}

// ==========================================================================
// Kernel 1: single-barrier software-pipelined filter/transpose + bf16 HMMA
// grid = 128 CTAs (one (b, 1024-t) unit each), 256 threads
// per iter:  [pre LDG early][post cp.async][wait] -> BAR ->
//            [produce tiles (kt-1)&1 : filter tid<128 | stmatrix tid>=128]
//            [MMA on tiles kt&1]           (ONE __syncthreads per iteration)
// ==========================================================================
__global__ __launch_bounds__(256)
void stdp_main(const float* __restrict__ pre, const float* __restrict__ post,
               const void* __restrict__ dtp)
{
    extern __shared__ char smem[];
    char* post_base = smem;                       // 4 slots [64 t][128 q] fp32

    const int tid  = threadIdx.x;
    const int lane = tid & 31;
    const int w    = tid >> 5;
    const int u    = blockIdx.x;
    const int b    = u >> 3;               // 8 units per batch
    const int t0   = (u & 7) * CHUNK;

    const float dt  = decode_dt(dtp);
    const float r   = expf(-dt / TAU_F);
    const float g0  = A_PLUS_F - A_MINUS_F;          // TAU_PLUS == TAU_MINUS
    const float c1  = r * g0;
    const float c60 = g0 * expf(-60.0f * dt / TAU_F);

    const char*  postg = (const char*)(post + (size_t)b * TT * 128);
    const float* preg  = pre + (size_t)b * TT * 128;

    // stage post block k -> ring slot k%4 (zero-fill past T), one commit group
    auto load_post = [&](int k) {
        const int tb0 = t0 + k * SC;
        #pragma unroll
        for (int i = tid; i < SC * 32; i += 256) {            // 2048 x 16B
            const int rr = i >> 5, c4 = i & 31;
            const int t  = tb0 + rr;
            const unsigned dst = smem_u32(post_base + (k & 3) * POST_SLOT_BYTES
                                          + rr * 512 + c4 * 16);
            const char* src = postg + ((size_t)(t < TT ? t : 0) * 512 + c4 * 16);
            const int ss = (t < TT) ? 16 : 0;
            asm volatile("cp.async.cg.shared.global [%0], [%1], 16, %2;\n"
                         :: "r"(dst), "l"(src), "r"(ss));
        }
        asm volatile("cp.async.commit_group;\n");
    };

    // pre block j -> registers (transpose warps only), {0,1} -> bf16 via PRMT (exact)
    unsigned regs[8][4];
    auto ldg_pre = [&](int j) {
        const int wi = w - 4;
        const float* pg = preg + (size_t)(t0 + j * SC) * 128;
        #pragma unroll
        for (int it = 0; it < 8; ++it) {
            const int tile = wi * 8 + it;
            const int tb = tile & 7;      // t block of 8
            const int pb = tile >> 3;     // p block of 32
            const int trow = tb * 8 + (lane >> 2);
            const int pc   = pb * 32 + 2 * (lane & 3);
            #pragma unroll
            for (int j2 = 0; j2 < 4; ++j2) {
                const float2 v = *(const float2*)(pg + (size_t)trow * 128 + pc + 8 * j2);
                regs[it][j2] = __byte_perm(__float_as_uint(v.x),
                                           __float_as_uint(v.y), 0x7632);
            }
        }
    };

    float hcarry = 0.0f;   // filter state (tid<128, one q each)
    float colsum = 0.0f;

    // produce tiles for block j into set j&1
    auto produce = [&](int j, bool init_carry) {
        char* preT_s = smem + OFF_TILES + (j & 1) * SET_BYTES;
        char* hT_s   = preT_s + TILE_BYTES;
        const float* cur = (const float*)(post_base + (j & 3) * POST_SLOT_BYTES);
        const float* nxt = (const float*)(post_base + ((j + 1) & 3) * POST_SLOT_BYTES);

        if (tid < 128) {
            // ---------- h filter (exact backward recurrence) -> hT bf16 ----------
            const int q = tid;
            if (init_carry) {
                float hh = 0.0f, wc = g0;
                #pragma unroll 4
                for (int tau = 1; tau < LWIN; ++tau) {
                    wc *= r;
                    hh += wc * nxt[(tau - 1) * 128 + q];
                }
                hcarry = hh;
            }
            #pragma unroll
            for (int g8 = SC / 8 - 1; g8 >= 0; --g8) {
                unsigned hp0 = 0, hp1 = 0, hp2 = 0, hp3 = 0, stash = 0;
                #pragma unroll
                for (int e = 7; e >= 0; --e) {
                    const int lt = g8 * 8 + e;
                    const unsigned uh =
                        (unsigned)__bfloat16_as_ushort(__float2bfloat16_rn(hcarry));
                    if (e & 1) stash = uh << 16;
                    else {
                        const unsigned wv = stash | uh;
                        if (e == 0) hp0 = wv; else if (e == 2) hp1 = wv;
                        else if (e == 4) hp2 = wv; else hp3 = wv;
                    }
                    const float s1  = cur[lt * 128 + q];
                    const float s60 = (lt < 5) ? cur[(lt + 59) * 128 + q]
                                               : nxt[(lt - 5) * 128 + q];
                    colsum += s1;        // exact integer column count
                    hcarry = fmaf(r, hcarry, fmaf(c1, s1, -c60 * s60));
                }
                // row q, 16B segment g8, swizzled packed layout
                const unsigned off = q * 128 + ((g8 << 4) ^ ((q & 7) << 4));
                uint4 v; v.x = hp0; v.y = hp1; v.z = hp2; v.w = hp3;
                *(uint4*)(hT_s + off) = v;
            }
        } else {
            // ---------- stmatrix regs -> preT[p][t] (swizzled packed) ----------
            const int wi = w - 4;
            #pragma unroll
            for (int it = 0; it < 8; ++it) {
                const int tile = wi * 8 + it;
                const int tb = tile & 7;
                const int pb = tile >> 3;
                const int row = pb * 32 + (lane >> 3) * 8 + (lane & 7);
                const unsigned daddr = smem_u32(
                    preT_s + row * 128 + (((unsigned)tb << 4) ^ (((unsigned)row & 7) << 4)));
                asm volatile(
                    "stmatrix.sync.aligned.m8n8.x4.trans.shared.b16 [%0], {%1,%2,%3,%4};\n"
                    :: "r"(daddr), "r"(regs[it][0]), "r"(regs[it][1]),
                       "r"(regs[it][2]), "r"(regs[it][3]));
            }
        }
    };

    // MMA accumulators: warp w -> p in [ (w&3)*32, +32 ), q in [ (w>>2)*64, +64 )
    float acc[2][8][4];
    #pragma unroll
    for (int mt = 0; mt < 2; ++mt)
        #pragma unroll
        for (int nt = 0; nt < 8; ++nt)
            #pragma unroll
            for (int c = 0; c < 4; ++c) acc[mt][nt][c] = 0.0f;

    const int pbase = (w & 3) * 32;
    const int qbase = (w >> 2) * 64;

    auto mma_set = [&](int s) {
        const char* preT_s = smem + OFF_TILES + s * SET_BYTES;
        const char* hT_s   = preT_s + TILE_BYTES;
        #pragma unroll
        for (int ks = 0; ks < SC / 16; ++ks) {
            const int k0 = ks * 16;
            unsigned a[2][4];
            #pragma unroll
            for (int mt = 0; mt < 2; ++mt) {
                const int arow  = pbase + mt * 16 + (lane & 15);
                const int abyte = (k0 + ((lane >> 4) << 3)) * 2;
                const unsigned aaddr = smem_u32(
                    preT_s + arow * 128 + (((unsigned)abyte) ^ (((unsigned)arow & 7) << 4)));
                asm volatile(
                    "ldmatrix.sync.aligned.m8n8.x4.shared.b16 {%0,%1,%2,%3}, [%4];\n"
                    : "=r"(a[mt][0]), "=r"(a[mt][1]), "=r"(a[mt][2]), "=r"(a[mt][3])
                    : "r"(aaddr));
            }
            #pragma unroll
            for (int nt = 0; nt < 8; ++nt) {
                const int brow  = qbase + nt * 8 + (lane & 7);
                const int bbyte = (k0 + (((lane >> 3) & 1) << 3)) * 2;
                const unsigned baddr = smem_u32(
                    hT_s + brow * 128 + (((unsigned)bbyte) ^ (((unsigned)brow & 7) << 4)));
                unsigned b0, b1;
                asm volatile(
                    "ldmatrix.sync.aligned.m8n8.x2.shared.b16 {%0,%1}, [%2];\n"
                    : "=r"(b0), "=r"(b1) : "r"(baddr));
                #pragma unroll
                for (int mt = 0; mt < 2; ++mt) {
                    asm volatile(
                        "mma.sync.aligned.m16n8k16.row.col.f32.bf16.bf16.f32 "
                        "{%0,%1,%2,%3}, {%4,%5,%6,%7}, {%8,%9}, {%0,%1,%2,%3};\n"
                        : "+f"(acc[mt][nt][0]), "+f"(acc[mt][nt][1]),
                          "+f"(acc[mt][nt][2]), "+f"(acc[mt][nt][3])
                        : "r"(a[mt][0]), "r"(a[mt][1]), "r"(a[mt][2]), "r"(a[mt][3]),
                          "r"(b0), "r"(b1));
                }
            }
        }
    };

    // ---------------- prologue ----------------
    load_post(NBLK);          // boundary block (hcarry init + s60 tail)
    load_post(NBLK - 1);
    if (w >= 4) ldg_pre(NBLK - 1);
    asm volatile("cp.async.wait_group 0;\n" ::: "memory");
    __syncthreads();
    produce(NBLK - 1, /*init_carry=*/true);      // tiles[1]
    load_post(NBLK - 2);                         // in flight: {NBLK-2}

    // ---------------- main loop: ONE barrier per iteration ----------------
    for (int kt = NBLK - 1; kt >= 0; --kt) {
        if (w >= 4 && kt >= 1) ldg_pre(kt - 1);          // early LDGs
        if (kt >= 2) load_post(kt - 2);                  // in flight: {kt-1, kt-2}
        if (kt >= 2)      asm volatile("cp.async.wait_group 1;\n" ::: "memory");
        else if (kt == 1) asm volatile("cp.async.wait_group 0;\n" ::: "memory");

        __syncthreads();
        // post(kt-1) visible; tiles[kt&1] produced last iter visible;
        // everyone's MMA on tiles[(kt-1)&1] (2 iters ago) done -> safe to overwrite

        if (kt >= 1) produce(kt - 1, false);             // writes tiles[(kt-1)&1]
        mma_set(kt & 1);                                 // reads  tiles[kt&1]
    }

    // ---- write per-CTA partials (deterministic parallel reduce later) ----
    {
        float* outp = g_partials + (size_t)u * NPRE * NPOST;
        #pragma unroll
        for (int mt = 0; mt < 2; ++mt) {
            #pragma unroll
            for (int nt = 0; nt < 8; ++nt) {
                const int p = pbase + mt * 16 + (lane >> 2);
                const int q = qbase + nt * 8 + 2 * (lane & 3);
                *(float2*)&outp[(size_t)p * 128 + q] =
                    make_float2(acc[mt][nt][0], acc[mt][nt][1]);
                *(float2*)&outp[(size_t)(p + 8) * 128 + q] =
                    make_float2(acc[mt][nt][2], acc[mt][nt][3]);
            }
        }
    }
    if (tid < 128) g_colsum_part[u * 128 + tid] = colsum;
}

// ==========================================================================
// Kernel 2: stage-1 partial reduce (128 arrays -> 8), fully parallel
// grid = 256 blocks (8 groups x 32 idx-chunks) x 128 threads; float4
// ==========================================================================
__global__ __launch_bounds__(128)
void reduce1()
{
    const int g  = blockIdx.x >> 5;                    // 0..7
    const int c  = blockIdx.x & 31;                    // 0..31
    const int i4 = c * 128 + threadIdx.x;              // float4 index 0..4095
    float4 s = make_float4(0.f, 0.f, 0.f, 0.f);
    #pragma unroll
    for (int a = 0; a < 16; ++a) {
        const float4 v = *(const float4*)
            &g_partials[(size_t)(g * 16 + a) * (NPRE * NPOST) + 4 * i4];
        s.x += v.x; s.y += v.y; s.z += v.z; s.w += v.w;
    }
    *(float4*)&g_part2[g * (NPRE * NPOST) + 4 * i4] = s;
}

// ==========================================================================
// Kernel 3: stage-2 reduce + inline homeostatic error + output
// grid = 64 x 256 (one output per thread)
// ==========================================================================
__global__ __launch_bounds__(256)
void finalize(const float* __restrict__ weights, float* __restrict__ out,
              const void* __restrict__ dtp)
{
    const int idx = blockIdx.x * blockDim.x + threadIdx.x;   // 0..16383 (p*128+q)
    const int q = idx & 127;

    // homeostatic rate error (fixed order; colsum array is L2-resident)
    float cs = 0.0f;
    #pragma unroll 8
    for (int i = 0; i < NCTA; ++i) cs += g_colsum_part[i * NPOST + q];
    const float dt    = decode_dt(dtp);
    const float alpha = dt / TAU_HOM;
    const float mean  = cs / (float)(BATCH * TT);
    const float err   = ((1.0f - alpha) * TARGET_RATE + alpha * mean) - TARGET_RATE;

    // fixed-order stage-2 reduce
    float s = 0.0f;
    #pragma unroll
    for (int g = 0; g < 8; ++g) s += g_part2[g * (NPRE * NPOST) + idx];

    const float inv = 1.0f / (float)(BATCH * TT);            // 2^-17 exact
    out[idx] = s * inv - HOM_RATE * err * weights[idx];
}

// ==========================================================================
extern "C" void kernel_launch(void* const* d_in, const int* in_sizes, int n_in,
                              void* d_out, int out_size)
{
    const float* pre     = (const float*)d_in[0];
    const float* post    = (const float*)d_in[1];
    const float* weights = (const float*)d_in[2];
    const void*  dtp     = (n_in > 3) ? d_in[3] : nullptr;

    cudaFuncSetAttribute(stdp_main, cudaFuncAttributeMaxDynamicSharedMemorySize, SMEM_BYTES);
    stdp_main<<<NCTA, 256, SMEM_BYTES>>>(pre, post, dtp);
    reduce1<<<256, 128>>>();
    finalize<<<(NPRE * NPOST) / 256, 256>>>(weights, (float*)d_out, dtp);
    (void)in_sizes; (void)out_size;
}